// round 1
// baseline (speedup 1.0000x reference)
#include <cuda_runtime.h>

#define NB   4
#define LSEQ 1024
#define DIM  512
#define NH   8
#define HDIM 4096

// -------- scratch (static device memory; no allocation) --------
__device__ float g_qh[(size_t)NB*NH*LSEQ*DIM];     // [B,H,L,D]
__device__ float g_kh[(size_t)NB*NH*LSEQ*DIM];
__device__ float g_vh[(size_t)NB*NH*LSEQ*DIM];
__device__ float g_attn[(size_t)NB*NH*LSEQ*LSEQ];  // [B,H,L,L] scores -> attn
__device__ float g_ctx[(size_t)NB*LSEQ*HDIM];      // [B,L,H*D]
__device__ float g_x[(size_t)NB*LSEQ*DIM];         // fc out + residual

constexpr int BM = 128, BN = 128, BK = 8;
constexpr float SCORE_SCALE = 0.044194173824159216f; // 1/sqrt(512)

// MODE 0: proj  C = X @ W^T        (NT, K=512)  -> g_qh/g_kh/g_vh (SEL) with [B,H,L,D] mapping
// MODE 1: score C = qh @ kh^T * s  (NT, K=512)  -> g_attn, per z=(b*H+h)
// MODE 2: ctx   C = attn @ vh      (NN, K=1024) -> g_ctx with [B,L,H*D] mapping, per z
// MODE 3: fc    C = ctx @ Wfc^T + bfc + resid (NT, K=4096) -> g_x
template<int MODE, int SEL>
__global__ __launch_bounds__(256)
void gemm_kernel(const float* __restrict__ X, const float* __restrict__ W,
                 const float* __restrict__ bias, const float* __restrict__ resid)
{
    constexpr int K   = (MODE <= 1) ? 512 : (MODE == 2 ? 1024 : 4096);
    constexpr int lda = K;
    constexpr bool TRB = (MODE != 2);
    constexpr int ldb = TRB ? K : 512;

    __shared__ float As[BK][BM + 4];
    __shared__ float Bs[BK][BN + 4];

    const int z = blockIdx.z;
    const float* A;
    const float* B;
    if (MODE == 0)      { A = X; B = W; }
    else if (MODE == 1) { A = g_qh + (size_t)z * LSEQ * DIM; B = g_kh + (size_t)z * LSEQ * DIM; }
    else if (MODE == 2) { A = g_attn + (size_t)z * LSEQ * LSEQ; B = g_vh + (size_t)z * LSEQ * DIM; }
    else                { A = g_ctx; B = W; }

    const int tid = threadIdx.x;
    const int tx = tid & 15, ty = tid >> 4;
    const int rowBase = blockIdx.y * BM;
    const int colBase = blockIdx.x * BN;

    const int aRow  = tid >> 1;          // 0..127
    const int aCol  = (tid & 1) * 4;     // 0 or 4
    const int bRowN = tid >> 5;          // 0..7   (NN)
    const int bColN = (tid & 31) * 4;    // 0..124 (NN)

    float acc[8][8];
#pragma unroll
    for (int i = 0; i < 8; i++)
#pragma unroll
        for (int j = 0; j < 8; j++) acc[i][j] = 0.f;

    const float* Aload  = A + (size_t)(rowBase + aRow) * lda + aCol;
    const float* BloadT = B + (size_t)(colBase + aRow) * ldb + aCol;
    const float* BloadN = B + (size_t)bRowN * ldb + colBase + bColN;

    for (int kt = 0; kt < K; kt += BK) {
        float4 a4 = *reinterpret_cast<const float4*>(Aload + kt);
        As[aCol + 0][aRow] = a4.x; As[aCol + 1][aRow] = a4.y;
        As[aCol + 2][aRow] = a4.z; As[aCol + 3][aRow] = a4.w;
        if (TRB) {
            float4 b4 = *reinterpret_cast<const float4*>(BloadT + kt);
            Bs[aCol + 0][aRow] = b4.x; Bs[aCol + 1][aRow] = b4.y;
            Bs[aCol + 2][aRow] = b4.z; Bs[aCol + 3][aRow] = b4.w;
        } else {
            float4 b4 = *reinterpret_cast<const float4*>(BloadN + (size_t)kt * ldb);
            *reinterpret_cast<float4*>(&Bs[bRowN][bColN]) = b4;
        }
        __syncthreads();
#pragma unroll
        for (int kk = 0; kk < BK; kk++) {
            float4 a0 = *reinterpret_cast<const float4*>(&As[kk][ty * 4]);
            float4 a1 = *reinterpret_cast<const float4*>(&As[kk][ty * 4 + 64]);
            float4 b0 = *reinterpret_cast<const float4*>(&Bs[kk][tx * 4]);
            float4 b1 = *reinterpret_cast<const float4*>(&Bs[kk][tx * 4 + 64]);
            float ra[8] = {a0.x, a0.y, a0.z, a0.w, a1.x, a1.y, a1.z, a1.w};
            float rb[8] = {b0.x, b0.y, b0.z, b0.w, b1.x, b1.y, b1.z, b1.w};
#pragma unroll
            for (int i = 0; i < 8; i++)
#pragma unroll
                for (int j = 0; j < 8; j++) acc[i][j] += ra[i] * rb[j];
        }
        __syncthreads();
    }

    // epilogue
#pragma unroll
    for (int ih = 0; ih < 2; ih++) {
#pragma unroll
        for (int ii = 0; ii < 4; ii++) {
            const int r = rowBase + ih * 64 + ty * 4 + ii;
#pragma unroll
            for (int jh = 0; jh < 2; jh++) {
                const int c = colBase + jh * 64 + tx * 4;
                float4 vv;
                vv.x = acc[ih * 4 + ii][jh * 4 + 0];
                vv.y = acc[ih * 4 + ii][jh * 4 + 1];
                vv.z = acc[ih * 4 + ii][jh * 4 + 2];
                vv.w = acc[ih * 4 + ii][jh * 4 + 3];
                if (MODE == 0) {
                    const int b = r >> 10, qi = r & 1023, h = c >> 9, e = c & 511;
                    float* C = (SEL == 0) ? g_qh : (SEL == 1) ? g_kh : g_vh;
                    *reinterpret_cast<float4*>(C + ((size_t)(b * NH + h) * LSEQ + qi) * DIM + e) = vv;
                } else if (MODE == 1) {
                    vv.x *= SCORE_SCALE; vv.y *= SCORE_SCALE; vv.z *= SCORE_SCALE; vv.w *= SCORE_SCALE;
                    *reinterpret_cast<float4*>(g_attn + (size_t)z * LSEQ * LSEQ + (size_t)r * LSEQ + c) = vv;
                } else if (MODE == 2) {
                    const int b = z >> 3, h = z & 7;
                    *reinterpret_cast<float4*>(g_ctx + (size_t)(b * LSEQ + r) * HDIM + h * DIM + c) = vv;
                } else {
                    float4 bb = *reinterpret_cast<const float4*>(bias + c);
                    float4 rr = *reinterpret_cast<const float4*>(resid + (size_t)r * DIM + c);
                    vv.x += bb.x + rr.x; vv.y += bb.y + rr.y;
                    vv.z += bb.z + rr.z; vv.w += bb.w + rr.w;
                    *reinterpret_cast<float4*>(g_x + (size_t)r * DIM + c) = vv;
                }
            }
        }
    }
}

// Masked softmax + renorm (allennlp semantics) for all 8 heads of one (b,q) row,
// fused head-mean written straight to the attn_mean output. Deterministic.
__global__ __launch_bounds__(256)
void softmax_kernel(const int* __restrict__ mask, float* __restrict__ mean_out)
{
    __shared__ float  sred[8];
    __shared__ float2 sred2[8];
    const int bq  = blockIdx.x;           // b*L + q
    const int b   = bq >> 10;
    const int qi  = bq & 1023;
    const int tid = threadIdx.x;
    const int lane = tid & 31, wid = tid >> 5;
    const int kc = tid * 4;

    int4 m4 = *reinterpret_cast<const int4*>(mask + (size_t)bq * LSEQ + kc);
    float mf[4] = {(float)m4.x, (float)m4.y, (float)m4.z, (float)m4.w};
    float macc[4] = {0.f, 0.f, 0.f, 0.f};

    for (int h = 0; h < NH; h++) {
        float* row = g_attn + (((size_t)b * NH + h) * LSEQ + qi) * LSEQ + kc;
        float4 s4 = *reinterpret_cast<const float4*>(row);
        float zf[4] = {mf[0] * s4.x, mf[1] * s4.y, mf[2] * s4.z, mf[3] * s4.w};
        float mx = fmaxf(fmaxf(zf[0], zf[1]), fmaxf(zf[2], zf[3]));
#pragma unroll
        for (int o = 16; o; o >>= 1) mx = fmaxf(mx, __shfl_xor_sync(0xffffffffu, mx, o));
        __syncthreads();                       // guard smem reuse across heads
        if (lane == 0) sred[wid] = mx;
        __syncthreads();
        float M = sred[0];
#pragma unroll
        for (int w = 1; w < 8; w++) M = fmaxf(M, sred[w]);

        float ef[4]; float sa = 0.f, sm = 0.f;
#pragma unroll
        for (int i = 0; i < 4; i++) { ef[i] = __expf(zf[i] - M); sa += ef[i]; sm += mf[i] * ef[i]; }
        float2 ss = make_float2(sa, sm);
#pragma unroll
        for (int o = 16; o; o >>= 1) {
            ss.x += __shfl_xor_sync(0xffffffffu, ss.x, o);
            ss.y += __shfl_xor_sync(0xffffffffu, ss.y, o);
        }
        if (lane == 0) sred2[wid] = ss;
        __syncthreads();
        float SA = 0.f, SM = 0.f;
#pragma unroll
        for (int w = 0; w < 8; w++) { SA += sred2[w].x; SM += sred2[w].y; }
        // attn_i = m_i * e_i / (SM + 1e-13 * SA)   (exact allennlp renorm algebra)
        const float inv = 1.0f / (SM + 1e-13f * SA);
        float4 o4;
        o4.x = mf[0] * ef[0] * inv; o4.y = mf[1] * ef[1] * inv;
        o4.z = mf[2] * ef[2] * inv; o4.w = mf[3] * ef[3] * inv;
        *reinterpret_cast<float4*>(row) = o4;
        macc[0] += o4.x; macc[1] += o4.y; macc[2] += o4.z; macc[3] += o4.w;
    }
    float4 mo = make_float4(macc[0] * 0.125f, macc[1] * 0.125f, macc[2] * 0.125f, macc[3] * 0.125f);
    *reinterpret_cast<float4*>(mean_out + (size_t)bq * LSEQ + kc) = mo;
}

__global__ __launch_bounds__(128)
void ln_kernel(const float* __restrict__ gamma, const float* __restrict__ beta,
               float* __restrict__ out)
{
    __shared__ float2 sred[4];
    const int r = blockIdx.x;
    const int tid = threadIdx.x, lane = tid & 31, wid = tid >> 5;
    float4 v = *reinterpret_cast<const float4*>(g_x + (size_t)r * DIM + tid * 4);
    float s  = v.x + v.y + v.z + v.w;
    float sq = v.x * v.x + v.y * v.y + v.z * v.z + v.w * v.w;
#pragma unroll
    for (int o = 16; o; o >>= 1) {
        s  += __shfl_xor_sync(0xffffffffu, s, o);
        sq += __shfl_xor_sync(0xffffffffu, sq, o);
    }
    if (lane == 0) sred[wid] = make_float2(s, sq);
    __syncthreads();
    float S = 0.f, SQ = 0.f;
#pragma unroll
    for (int w = 0; w < 4; w++) { S += sred[w].x; SQ += sred[w].y; }
    const float mu = S * (1.f / DIM);
    const float var = SQ * (1.f / DIM) - mu * mu;
    const float rstd = rsqrtf(var + 1e-5f);
    float4 g  = *reinterpret_cast<const float4*>(gamma + tid * 4);
    float4 bt = *reinterpret_cast<const float4*>(beta + tid * 4);
    float4 o;
    o.x = (v.x - mu) * rstd * g.x + bt.x;
    o.y = (v.y - mu) * rstd * g.y + bt.y;
    o.z = (v.z - mu) * rstd * g.z + bt.z;
    o.w = (v.w - mu) * rstd * g.w + bt.w;
    *reinterpret_cast<float4*>(out + (size_t)r * DIM + tid * 4) = o;
}

extern "C" void kernel_launch(void* const* d_in, const int* in_sizes, int n_in,
                              void* d_out, int out_size)
{
    const float* q     = (const float*)d_in[0];
    const int*   mask  = (const int*)  d_in[1];
    const float* k     = (const float*)d_in[2];
    const float* v     = (const float*)d_in[3];
    const float* Wq    = (const float*)d_in[4];
    const float* Wk    = (const float*)d_in[5];
    const float* Wv    = (const float*)d_in[6];
    const float* Wfc   = (const float*)d_in[7];
    const float* bfc   = (const float*)d_in[8];
    const float* gamma = (const float*)d_in[9];
    const float* beta  = (const float*)d_in[10];

    float* out      = (float*)d_out;                      // [B,L,D]
    float* mean_out = out + (size_t)NB * LSEQ * DIM;      // [B,L,L]

    dim3 thr(256);
    // projections: [4096,512] @ [512,4096]^T
    gemm_kernel<0, 0><<<dim3(32, 32, 1), thr>>>(q, Wq, nullptr, nullptr);
    gemm_kernel<0, 1><<<dim3(32, 32, 1), thr>>>(k, Wk, nullptr, nullptr);
    gemm_kernel<0, 2><<<dim3(32, 32, 1), thr>>>(v, Wv, nullptr, nullptr);
    // scores: per (b,h) [1024,512] @ [512,1024]
    gemm_kernel<1, 0><<<dim3(8, 8, 32), thr>>>(nullptr, nullptr, nullptr, nullptr);
    // masked softmax + renorm + head mean
    softmax_kernel<<<dim3(NB * LSEQ), 256>>>(mask, mean_out);
    // context: per (b,h) [1024,1024] @ [1024,512]
    gemm_kernel<2, 0><<<dim3(4, 8, 32), thr>>>(nullptr, nullptr, nullptr, nullptr);
    // fc + bias + residual
    gemm_kernel<3, 0><<<dim3(4, 32, 1), thr>>>(nullptr, Wfc, bfc, q);
    // layernorm -> final out
    ln_kernel<<<dim3(NB * LSEQ), 128>>>(gamma, beta, out);
}

// round 5
// speedup vs baseline: 1.8111x; 1.8111x over previous
#include <cuda_runtime.h>

#define NB   4
#define LSEQ 1024
#define DIM  512
#define NH   8
#define HDIM 4096

// -------- scratch (static device memory; no allocation) --------
__device__ float g_qh[(size_t)NB*NH*LSEQ*DIM];     // [B,H,L,D]
__device__ float g_kh[(size_t)NB*NH*LSEQ*DIM];
__device__ float g_vh[(size_t)NB*NH*LSEQ*DIM];
__device__ float g_attn[(size_t)NB*NH*LSEQ*LSEQ];  // [B,H,L,L] scores -> attn
__device__ float g_ctx[(size_t)NB*LSEQ*HDIM];      // [B,L,H*D]
__device__ float g_x[(size_t)NB*LSEQ*DIM];         // fc out + residual

constexpr int BM = 128, BN = 128, BK = 16;
constexpr float SCORE_SCALE = 0.044194173824159216f; // 1/sqrt(512)

__device__ __forceinline__ unsigned f2tf(float x) {
    unsigned u;
    asm("cvt.rna.tf32.f32 %0, %1;" : "=r"(u) : "f"(x));
    return u;
}

__device__ __forceinline__ void mma_tf32(float* d, const unsigned* a, const unsigned* b) {
    asm volatile(
        "mma.sync.aligned.m16n8k8.row.col.f32.tf32.tf32.f32 "
        "{%0,%1,%2,%3}, {%4,%5,%6,%7}, {%8,%9}, {%0,%1,%2,%3};"
        : "+f"(d[0]), "+f"(d[1]), "+f"(d[2]), "+f"(d[3])
        : "r"(a[0]), "r"(a[1]), "r"(a[2]), "r"(a[3]), "r"(b[0]), "r"(b[1]));
}

// MODE 0: proj  C = X @ W^T        (NT, K=512)  -> g_qh/g_kh/g_vh (SEL), [B,H,L,D] mapping
// MODE 1: score C = qh @ kh^T * s  (NT, K=512)  -> g_attn, per z=(b*H+h)
// MODE 2: ctx   C = attn @ vh      (NN, K=1024) -> g_ctx [B,L,H*D], per z
// MODE 3: fc    C = ctx @ Wfc^T + bfc + resid (NT, K=4096) -> g_x
template<int MODE, int SEL>
__global__ __launch_bounds__(256)
void gemm_kernel(const float* __restrict__ X, const float* __restrict__ W,
                 const float* __restrict__ bias, const float* __restrict__ resid)
{
    constexpr int K   = (MODE <= 1) ? 512 : (MODE == 2 ? 1024 : 4096);
    constexpr int lda = K;
    constexpr bool TRB = (MODE != 2);
    constexpr int ldb = TRB ? K : 512;

    __shared__ unsigned As[BK][BM + 4];   // tf32 bits, [k][m]
    __shared__ unsigned Bs[BK][BN + 4];   // tf32 bits, [k][n]

    const int z = blockIdx.z;
    const float* A;
    const float* B;
    if (MODE == 0)      { A = X; B = W; }
    else if (MODE == 1) { A = g_qh + (size_t)z * LSEQ * DIM; B = g_kh + (size_t)z * LSEQ * DIM; }
    else if (MODE == 2) { A = g_attn + (size_t)z * LSEQ * LSEQ; B = g_vh + (size_t)z * LSEQ * DIM; }
    else                { A = g_ctx; B = W; }

    const int tid  = threadIdx.x;
    const int lane = tid & 31;
    const int warp = tid >> 5;
    const int gid  = lane >> 2;     // 0..7
    const int tig  = lane & 3;      // 0..3
    const int warpM = (warp & 1) * 64;
    const int warpN = (warp >> 1) * 32;

    const int rowBase = blockIdx.y * BM;
    const int colBase = blockIdx.x * BN;

    // global->smem mapping (transpose path, K-contiguous loads)
    const int aRow  = tid >> 1;           // 0..127
    const int aColB = (tid & 1) * 8;      // 0 or 8
    // NN B mapping (MODE 2)
    const int bRowN = tid >> 5;           // 0..7 (and +8)
    const int bColN = (tid & 31) * 4;

    float acc[4][4][4];
#pragma unroll
    for (int mi = 0; mi < 4; mi++)
#pragma unroll
        for (int nj = 0; nj < 4; nj++)
#pragma unroll
            for (int r = 0; r < 4; r++) acc[mi][nj][r] = 0.f;

    const float* Aload  = A + (size_t)(rowBase + aRow) * lda + aColB;
    const float* BloadT = B + (size_t)(colBase + aRow) * ldb + aColB;
    const float* BloadN = B + (size_t)bRowN * ldb + colBase + bColN;

    for (int kt = 0; kt < K; kt += BK) {
#pragma unroll
        for (int j = 0; j < 2; j++) {
            float4 a4 = *reinterpret_cast<const float4*>(Aload + kt + j * 4);
            As[aColB + j * 4 + 0][aRow] = f2tf(a4.x);
            As[aColB + j * 4 + 1][aRow] = f2tf(a4.y);
            As[aColB + j * 4 + 2][aRow] = f2tf(a4.z);
            As[aColB + j * 4 + 3][aRow] = f2tf(a4.w);
        }
        if (TRB) {
#pragma unroll
            for (int j = 0; j < 2; j++) {
                float4 b4 = *reinterpret_cast<const float4*>(BloadT + kt + j * 4);
                Bs[aColB + j * 4 + 0][aRow] = f2tf(b4.x);
                Bs[aColB + j * 4 + 1][aRow] = f2tf(b4.y);
                Bs[aColB + j * 4 + 2][aRow] = f2tf(b4.z);
                Bs[aColB + j * 4 + 3][aRow] = f2tf(b4.w);
            }
        } else {
#pragma unroll
            for (int j = 0; j < 2; j++) {
                const int r = bRowN + j * 8;
                float4 b4 = *reinterpret_cast<const float4*>(BloadN + (size_t)(kt + j * 8) * ldb);
                Bs[r][bColN + 0] = f2tf(b4.x);
                Bs[r][bColN + 1] = f2tf(b4.y);
                Bs[r][bColN + 2] = f2tf(b4.z);
                Bs[r][bColN + 3] = f2tf(b4.w);
            }
        }
        __syncthreads();

#pragma unroll
        for (int ks = 0; ks < BK; ks += 8) {
            unsigned af[4][4], bf[4][2];
#pragma unroll
            for (int mi = 0; mi < 4; mi++) {
                const int m = warpM + mi * 16 + gid;
                af[mi][0] = As[ks + tig][m];
                af[mi][1] = As[ks + tig][m + 8];
                af[mi][2] = As[ks + tig + 4][m];
                af[mi][3] = As[ks + tig + 4][m + 8];
            }
#pragma unroll
            for (int nj = 0; nj < 4; nj++) {
                const int n = warpN + nj * 8 + gid;
                bf[nj][0] = Bs[ks + tig][n];
                bf[nj][1] = Bs[ks + tig + 4][n];
            }
#pragma unroll
            for (int mi = 0; mi < 4; mi++)
#pragma unroll
                for (int nj = 0; nj < 4; nj++)
                    mma_tf32(acc[mi][nj], af[mi], bf[nj]);
        }
        __syncthreads();
    }

    // epilogue: each (mi,nj) owns rows {r0, r0+8}, cols {c, c+1}
#pragma unroll
    for (int mi = 0; mi < 4; mi++) {
#pragma unroll
        for (int nj = 0; nj < 4; nj++) {
#pragma unroll
            for (int half = 0; half < 2; half++) {
                const int r = rowBase + warpM + mi * 16 + gid + half * 8;
                const int c = colBase + warpN + nj * 8 + 2 * tig;
                float2 vv = make_float2(acc[mi][nj][half * 2 + 0],
                                        acc[mi][nj][half * 2 + 1]);
                if (MODE == 0) {
                    const int b = r >> 10, qi = r & 1023, h = c >> 9, e = c & 511;
                    float* C = (SEL == 0) ? g_qh : (SEL == 1) ? g_kh : g_vh;
                    *reinterpret_cast<float2*>(C + ((size_t)(b * NH + h) * LSEQ + qi) * DIM + e) = vv;
                } else if (MODE == 1) {
                    vv.x *= SCORE_SCALE; vv.y *= SCORE_SCALE;
                    *reinterpret_cast<float2*>(g_attn + (size_t)z * LSEQ * LSEQ + (size_t)r * LSEQ + c) = vv;
                } else if (MODE == 2) {
                    const int b = z >> 3, h = z & 7;
                    *reinterpret_cast<float2*>(g_ctx + (size_t)(b * LSEQ + r) * HDIM + h * DIM + c) = vv;
                } else {
                    float2 bb = *reinterpret_cast<const float2*>(bias + c);
                    float2 rr = *reinterpret_cast<const float2*>(resid + (size_t)r * DIM + c);
                    vv.x += bb.x + rr.x; vv.y += bb.y + rr.y;
                    *reinterpret_cast<float2*>(g_x + (size_t)r * DIM + c) = vv;
                }
            }
        }
    }
}

// Masked softmax + renorm (allennlp semantics) for all 8 heads of one (b,q) row,
// fused head-mean written straight to the attn_mean output. Deterministic.
__global__ __launch_bounds__(256)
void softmax_kernel(const int* __restrict__ mask, float* __restrict__ mean_out)
{
    __shared__ float  sred[8];
    __shared__ float2 sred2[8];
    const int bq  = blockIdx.x;           // b*L + q
    const int b   = bq >> 10;
    const int qi  = bq & 1023;
    const int tid = threadIdx.x;
    const int lane = tid & 31, wid = tid >> 5;
    const int kc = tid * 4;

    int4 m4 = *reinterpret_cast<const int4*>(mask + (size_t)bq * LSEQ + kc);
    float mf[4] = {(float)m4.x, (float)m4.y, (float)m4.z, (float)m4.w};
    float macc[4] = {0.f, 0.f, 0.f, 0.f};

    for (int h = 0; h < NH; h++) {
        float* row = g_attn + (((size_t)b * NH + h) * LSEQ + qi) * LSEQ + kc;
        float4 s4 = *reinterpret_cast<const float4*>(row);
        float zf[4] = {mf[0] * s4.x, mf[1] * s4.y, mf[2] * s4.z, mf[3] * s4.w};
        float mx = fmaxf(fmaxf(zf[0], zf[1]), fmaxf(zf[2], zf[3]));
#pragma unroll
        for (int o = 16; o; o >>= 1) mx = fmaxf(mx, __shfl_xor_sync(0xffffffffu, mx, o));
        __syncthreads();                       // guard smem reuse across heads
        if (lane == 0) sred[wid] = mx;
        __syncthreads();
        float M = sred[0];
#pragma unroll
        for (int w = 1; w < 8; w++) M = fmaxf(M, sred[w]);

        float ef[4]; float sa = 0.f, sm = 0.f;
#pragma unroll
        for (int i = 0; i < 4; i++) { ef[i] = __expf(zf[i] - M); sa += ef[i]; sm += mf[i] * ef[i]; }
        float2 ss = make_float2(sa, sm);
#pragma unroll
        for (int o = 16; o; o >>= 1) {
            ss.x += __shfl_xor_sync(0xffffffffu, ss.x, o);
            ss.y += __shfl_xor_sync(0xffffffffu, ss.y, o);
        }
        if (lane == 0) sred2[wid] = ss;
        __syncthreads();
        float SA = 0.f, SM = 0.f;
#pragma unroll
        for (int w = 0; w < 8; w++) { SA += sred2[w].x; SM += sred2[w].y; }
        // attn_i = m_i * e_i / (SM + 1e-13 * SA)   (exact allennlp renorm algebra)
        const float inv = 1.0f / (SM + 1e-13f * SA);
        float4 o4;
        o4.x = mf[0] * ef[0] * inv; o4.y = mf[1] * ef[1] * inv;
        o4.z = mf[2] * ef[2] * inv; o4.w = mf[3] * ef[3] * inv;
        *reinterpret_cast<float4*>(row) = o4;
        macc[0] += o4.x; macc[1] += o4.y; macc[2] += o4.z; macc[3] += o4.w;
    }
    float4 mo = make_float4(macc[0] * 0.125f, macc[1] * 0.125f, macc[2] * 0.125f, macc[3] * 0.125f);
    *reinterpret_cast<float4*>(mean_out + (size_t)bq * LSEQ + kc) = mo;
}

__global__ __launch_bounds__(128)
void ln_kernel(const float* __restrict__ gamma, const float* __restrict__ beta,
               float* __restrict__ out)
{
    __shared__ float2 sred[4];
    const int r = blockIdx.x;
    const int tid = threadIdx.x, lane = tid & 31, wid = tid >> 5;
    float4 v = *reinterpret_cast<const float4*>(g_x + (size_t)r * DIM + tid * 4);
    float s  = v.x + v.y + v.z + v.w;
    float sq = v.x * v.x + v.y * v.y + v.z * v.z + v.w * v.w;
#pragma unroll
    for (int o = 16; o; o >>= 1) {
        s  += __shfl_xor_sync(0xffffffffu, s, o);
        sq += __shfl_xor_sync(0xffffffffu, sq, o);
    }
    if (lane == 0) sred[wid] = make_float2(s, sq);
    __syncthreads();
    float S = 0.f, SQ = 0.f;
#pragma unroll
    for (int w = 0; w < 4; w++) { S += sred[w].x; SQ += sred[w].y; }
    const float mu = S * (1.f / DIM);
    const float var = SQ * (1.f / DIM) - mu * mu;
    const float rstd = rsqrtf(var + 1e-5f);
    float4 g  = *reinterpret_cast<const float4*>(gamma + tid * 4);
    float4 bt = *reinterpret_cast<const float4*>(beta + tid * 4);
    float4 o;
    o.x = (v.x - mu) * rstd * g.x + bt.x;
    o.y = (v.y - mu) * rstd * g.y + bt.y;
    o.z = (v.z - mu) * rstd * g.z + bt.z;
    o.w = (v.w - mu) * rstd * g.w + bt.w;
    *reinterpret_cast<float4*>(out + (size_t)r * DIM + tid * 4) = o;
}

extern "C" void kernel_launch(void* const* d_in, const int* in_sizes, int n_in,
                              void* d_out, int out_size)
{
    const float* q     = (const float*)d_in[0];
    const int*   mask  = (const int*)  d_in[1];
    const float* k     = (const float*)d_in[2];
    const float* v     = (const float*)d_in[3];
    const float* Wq    = (const float*)d_in[4];
    const float* Wk    = (const float*)d_in[5];
    const float* Wv    = (const float*)d_in[6];
    const float* Wfc   = (const float*)d_in[7];
    const float* bfc   = (const float*)d_in[8];
    const float* gamma = (const float*)d_in[9];
    const float* beta  = (const float*)d_in[10];

    float* out      = (float*)d_out;                      // [B,L,D]
    float* mean_out = out + (size_t)NB * LSEQ * DIM;      // [B,L,L]

    dim3 thr(256);
    // projections: [4096,512] @ [512,4096]^T
    gemm_kernel<0, 0><<<dim3(32, 32, 1), thr>>>(q, Wq, nullptr, nullptr);
    gemm_kernel<0, 1><<<dim3(32, 32, 1), thr>>>(k, Wk, nullptr, nullptr);
    gemm_kernel<0, 2><<<dim3(32, 32, 1), thr>>>(v, Wv, nullptr, nullptr);
    // scores: per (b,h) [1024,512] @ [512,1024]
    gemm_kernel<1, 0><<<dim3(8, 8, 32), thr>>>(nullptr, nullptr, nullptr, nullptr);
    // masked softmax + renorm + head mean
    softmax_kernel<<<dim3(NB * LSEQ), 256>>>(mask, mean_out);
    // context: per (b,h) [1024,1024] @ [1024,512]
    gemm_kernel<2, 0><<<dim3(4, 8, 32), thr>>>(nullptr, nullptr, nullptr, nullptr);
    // fc + bias + residual
    gemm_kernel<3, 0><<<dim3(4, 32, 1), thr>>>(nullptr, Wfc, bfc, q);
    // layernorm -> final out
    ln_kernel<<<dim3(NB * LSEQ), 128>>>(gamma, beta, out);
}

// round 14
// speedup vs baseline: 2.0117x; 1.1108x over previous
#include <cuda_runtime.h>

#define NB   4
#define LSEQ 1024
#define DIM  512
#define NH   8
#define HDIM 4096

// -------- scratch (static device memory; no allocation) --------
__device__ float g_qh[(size_t)NB*NH*LSEQ*DIM];     // [B,H,L,D]
__device__ float g_kh[(size_t)NB*NH*LSEQ*DIM];
__device__ float g_vh[(size_t)NB*NH*LSEQ*DIM];
__device__ float g_attn[(size_t)NB*NH*LSEQ*LSEQ];  // [B,H,L,L] scores -> attn
__device__ float g_ctx[(size_t)NB*LSEQ*HDIM];      // [B,L,H*D]
__device__ float g_x[(size_t)NB*LSEQ*DIM];         // fc out + residual

constexpr int BM = 128, BN = 128, BK = 16;
constexpr int AS_STRIDE = BK + 4;    // [m][k] row stride 20 -> conflict-free frag loads
constexpr int BT_STRIDE = BK + 4;    // [n][k] row stride 20
constexpr int BNN_STRIDE = BN + 8;   // [k][n] row stride 136 (mode 2)
constexpr float SCORE_SCALE = 0.044194173824159216f; // 1/sqrt(512)

__device__ __forceinline__ unsigned f2tf(float x) {
    unsigned u;
    asm("cvt.rna.tf32.f32 %0, %1;" : "=r"(u) : "f"(x));
    return u;
}

__device__ __forceinline__ void mma_tf32(float* d, const unsigned* a, const unsigned* b) {
    asm volatile(
        "mma.sync.aligned.m16n8k8.row.col.f32.tf32.tf32.f32 "
        "{%0,%1,%2,%3}, {%4,%5,%6,%7}, {%8,%9}, {%0,%1,%2,%3};"
        : "+f"(d[0]), "+f"(d[1]), "+f"(d[2]), "+f"(d[3])
        : "r"(a[0]), "r"(a[1]), "r"(a[2]), "r"(a[3]), "r"(b[0]), "r"(b[1]));
}

__device__ __forceinline__ void cpasync16(float* dst, const float* src) {
    unsigned s = (unsigned)__cvta_generic_to_shared(dst);
    asm volatile("cp.async.ca.shared.global [%0], [%1], 16;" :: "r"(s), "l"(src));
}
#define CP_COMMIT()  asm volatile("cp.async.commit_group;")
#define CP_WAIT1()   asm volatile("cp.async.wait_group 1;")

// MODE 0: proj  C = X @ W^T        (NT, K=512)  -> g_qh/g_kh/g_vh (SEL), [B,H,L,D] mapping
// MODE 1: score C = qh @ kh^T * s  (NT, K=512)  -> g_attn, per z=(b*H+h)
// MODE 2: ctx   C = attn @ vh      (NN, K=1024) -> g_ctx [B,L,H*D], per z
// MODE 3: fc    C = ctx @ Wfc^T + bfc + resid (NT, K=4096) -> g_x
template<int MODE, int SEL>
__global__ __launch_bounds__(128, 2)
void gemm_kernel(const float* __restrict__ X, const float* __restrict__ W,
                 const float* __restrict__ bias, const float* __restrict__ resid)
{
    constexpr int K   = (MODE <= 1) ? 512 : (MODE == 2 ? 1024 : 4096);
    constexpr int lda = K;
    constexpr bool TRB = (MODE != 2);
    constexpr int ldb = TRB ? K : 512;
    constexpr int NT  = K / BK;
    constexpr int BS_ELEMS = TRB ? (BN * BT_STRIDE) : (BK * BNN_STRIDE);

    __shared__ float As[2][BM * AS_STRIDE];
    __shared__ float Bs[2][BS_ELEMS];

    const int z = blockIdx.z;
    const float* A;
    const float* B;
    if (MODE == 0)      { A = X; B = W; }
    else if (MODE == 1) { A = g_qh + (size_t)z * LSEQ * DIM; B = g_kh + (size_t)z * LSEQ * DIM; }
    else if (MODE == 2) { A = g_attn + (size_t)z * LSEQ * LSEQ; B = g_vh + (size_t)z * LSEQ * DIM; }
    else                { A = g_ctx; B = W; }

    const int tid  = threadIdx.x;
    const int lane = tid & 31;
    const int warp = tid >> 5;          // 0..3
    const int gid  = lane >> 2;         // 0..7
    const int tig  = lane & 3;          // 0..3
    const int warpM = (warp & 1) * 64;
    const int warpN = (warp >> 1) * 64;

    const int rowBase = blockIdx.y * BM;
    const int colBase = blockIdx.x * BN;

    // global source pointers for async copies
    const float* Arow = A + (size_t)(rowBase + tid) * lda;              // [m][k] rows
    const float* Brow_t = B + (size_t)(colBase + tid) * ldb;            // TRB: [n][k] rows
    const float* Brow_n = B + (size_t)(tid >> 3) * ldb                   // NN: [k][n] rows
                            + colBase + (tid & 7) * 16;

    float acc[4][8][4];
#pragma unroll
    for (int mi = 0; mi < 4; mi++)
#pragma unroll
        for (int nj = 0; nj < 8; nj++)
#pragma unroll
            for (int r = 0; r < 4; r++) acc[mi][nj][r] = 0.f;

    auto issue_tile = [&](int st, int kt) {
#pragma unroll
        for (int c = 0; c < 4; c++)
            cpasync16(&As[st][tid * AS_STRIDE + c * 4], Arow + kt + c * 4);
        if (TRB) {
#pragma unroll
            for (int c = 0; c < 4; c++)
                cpasync16(&Bs[st][tid * BT_STRIDE + c * 4], Brow_t + kt + c * 4);
        } else {
#pragma unroll
            for (int c = 0; c < 4; c++)
                cpasync16(&Bs[st][(tid >> 3) * BNN_STRIDE + (tid & 7) * 16 + c * 4],
                          Brow_n + (size_t)kt * ldb + c * 4);
        }
    };

    issue_tile(0, 0);
    CP_COMMIT();

    for (int t = 0; t < NT; t++) {
        if (t + 1 < NT) issue_tile((t + 1) & 1, (t + 1) * BK);
        CP_COMMIT();
        CP_WAIT1();
        __syncthreads();

        const int st = t & 1;
#pragma unroll
        for (int ks = 0; ks < BK; ks += 8) {
            unsigned af[4][4], bf[8][2];
#pragma unroll
            for (int mi = 0; mi < 4; mi++) {
                const int m0 = warpM + mi * 16 + gid;
                af[mi][0] = f2tf(As[st][(m0)     * AS_STRIDE + ks + tig]);
                af[mi][1] = f2tf(As[st][(m0 + 8) * AS_STRIDE + ks + tig]);
                af[mi][2] = f2tf(As[st][(m0)     * AS_STRIDE + ks + tig + 4]);
                af[mi][3] = f2tf(As[st][(m0 + 8) * AS_STRIDE + ks + tig + 4]);
            }
#pragma unroll
            for (int nj = 0; nj < 8; nj++) {
                const int n0 = warpN + nj * 8 + gid;
                if (TRB) {
                    bf[nj][0] = f2tf(Bs[st][n0 * BT_STRIDE + ks + tig]);
                    bf[nj][1] = f2tf(Bs[st][n0 * BT_STRIDE + ks + tig + 4]);
                } else {
                    bf[nj][0] = f2tf(Bs[st][(ks + tig)     * BNN_STRIDE + n0]);
                    bf[nj][1] = f2tf(Bs[st][(ks + tig + 4) * BNN_STRIDE + n0]);
                }
            }
#pragma unroll
            for (int mi = 0; mi < 4; mi++)
#pragma unroll
                for (int nj = 0; nj < 8; nj++)
                    mma_tf32(acc[mi][nj], af[mi], bf[nj]);
        }
        __syncthreads();
    }

    // epilogue: each (mi,nj) owns rows {r0, r0+8}, cols {c, c+1}
#pragma unroll
    for (int mi = 0; mi < 4; mi++) {
#pragma unroll
        for (int nj = 0; nj < 8; nj++) {
#pragma unroll
            for (int half = 0; half < 2; half++) {
                const int r = rowBase + warpM + mi * 16 + gid + half * 8;
                const int c = colBase + warpN + nj * 8 + 2 * tig;
                float2 vv = make_float2(acc[mi][nj][half * 2 + 0],
                                        acc[mi][nj][half * 2 + 1]);
                if (MODE == 0) {
                    const int b = r >> 10, qi = r & 1023, h = c >> 9, e = c & 511;
                    float* C = (SEL == 0) ? g_qh : (SEL == 1) ? g_kh : g_vh;
                    *reinterpret_cast<float2*>(C + ((size_t)(b * NH + h) * LSEQ + qi) * DIM + e) = vv;
                } else if (MODE == 1) {
                    vv.x *= SCORE_SCALE; vv.y *= SCORE_SCALE;
                    *reinterpret_cast<float2*>(g_attn + (size_t)z * LSEQ * LSEQ + (size_t)r * LSEQ + c) = vv;
                } else if (MODE == 2) {
                    const int b = z >> 3, h = z & 7;
                    *reinterpret_cast<float2*>(g_ctx + (size_t)(b * LSEQ + r) * HDIM + h * DIM + c) = vv;
                } else {
                    float2 bb = *reinterpret_cast<const float2*>(bias + c);
                    float2 rr = *reinterpret_cast<const float2*>(resid + (size_t)r * DIM + c);
                    vv.x += bb.x + rr.x; vv.y += bb.y + rr.y;
                    *reinterpret_cast<float2*>(g_x + (size_t)r * DIM + c) = vv;
                }
            }
        }
    }
}

// Masked softmax + renorm (allennlp semantics) for all 8 heads of one (b,q) row,
// fused head-mean written straight to the attn_mean output. Deterministic.
__global__ __launch_bounds__(256)
void softmax_kernel(const int* __restrict__ mask, float* __restrict__ mean_out)
{
    __shared__ float  sred[8];
    __shared__ float2 sred2[8];
    const int bq  = blockIdx.x;           // b*L + q
    const int b   = bq >> 10;
    const int qi  = bq & 1023;
    const int tid = threadIdx.x;
    const int lane = tid & 31, wid = tid >> 5;
    const int kc = tid * 4;

    int4 m4 = *reinterpret_cast<const int4*>(mask + (size_t)bq * LSEQ + kc);
    float mf[4] = {(float)m4.x, (float)m4.y, (float)m4.z, (float)m4.w};
    float macc[4] = {0.f, 0.f, 0.f, 0.f};

    for (int h = 0; h < NH; h++) {
        float* row = g_attn + (((size_t)b * NH + h) * LSEQ + qi) * LSEQ + kc;
        float4 s4 = *reinterpret_cast<const float4*>(row);
        float zf[4] = {mf[0] * s4.x, mf[1] * s4.y, mf[2] * s4.z, mf[3] * s4.w};
        float mx = fmaxf(fmaxf(zf[0], zf[1]), fmaxf(zf[2], zf[3]));
#pragma unroll
        for (int o = 16; o; o >>= 1) mx = fmaxf(mx, __shfl_xor_sync(0xffffffffu, mx, o));
        __syncthreads();                       // guard smem reuse across heads
        if (lane == 0) sred[wid] = mx;
        __syncthreads();
        float M = sred[0];
#pragma unroll
        for (int w = 1; w < 8; w++) M = fmaxf(M, sred[w]);

        float ef[4]; float sa = 0.f, sm = 0.f;
#pragma unroll
        for (int i = 0; i < 4; i++) { ef[i] = __expf(zf[i] - M); sa += ef[i]; sm += mf[i] * ef[i]; }
        float2 ss = make_float2(sa, sm);
#pragma unroll
        for (int o = 16; o; o >>= 1) {
            ss.x += __shfl_xor_sync(0xffffffffu, ss.x, o);
            ss.y += __shfl_xor_sync(0xffffffffu, ss.y, o);
        }
        if (lane == 0) sred2[wid] = ss;
        __syncthreads();
        float SA = 0.f, SM = 0.f;
#pragma unroll
        for (int w = 0; w < 8; w++) { SA += sred2[w].x; SM += sred2[w].y; }
        // attn_i = m_i * e_i / (SM + 1e-13 * SA)   (exact allennlp renorm algebra)
        const float inv = 1.0f / (SM + 1e-13f * SA);
        float4 o4;
        o4.x = mf[0] * ef[0] * inv; o4.y = mf[1] * ef[1] * inv;
        o4.z = mf[2] * ef[2] * inv; o4.w = mf[3] * ef[3] * inv;
        *reinterpret_cast<float4*>(row) = o4;
        macc[0] += o4.x; macc[1] += o4.y; macc[2] += o4.z; macc[3] += o4.w;
    }
    float4 mo = make_float4(macc[0] * 0.125f, macc[1] * 0.125f, macc[2] * 0.125f, macc[3] * 0.125f);
    *reinterpret_cast<float4*>(mean_out + (size_t)bq * LSEQ + kc) = mo;
}

__global__ __launch_bounds__(128)
void ln_kernel(const float* __restrict__ gamma, const float* __restrict__ beta,
               float* __restrict__ out)
{
    __shared__ float2 sred[4];
    const int r = blockIdx.x;
    const int tid = threadIdx.x, lane = tid & 31, wid = tid >> 5;
    float4 v = *reinterpret_cast<const float4*>(g_x + (size_t)r * DIM + tid * 4);
    float s  = v.x + v.y + v.z + v.w;
    float sq = v.x * v.x + v.y * v.y + v.z * v.z + v.w * v.w;
#pragma unroll
    for (int o = 16; o; o >>= 1) {
        s  += __shfl_xor_sync(0xffffffffu, s, o);
        sq += __shfl_xor_sync(0xffffffffu, sq, o);
    }
    if (lane == 0) sred[wid] = make_float2(s, sq);
    __syncthreads();
    float S = 0.f, SQ = 0.f;
#pragma unroll
    for (int w = 0; w < 4; w++) { S += sred[w].x; SQ += sred[w].y; }
    const float mu = S * (1.f / DIM);
    const float var = SQ * (1.f / DIM) - mu * mu;
    const float rstd = rsqrtf(var + 1e-5f);
    float4 g  = *reinterpret_cast<const float4*>(gamma + tid * 4);
    float4 bt = *reinterpret_cast<const float4*>(beta + tid * 4);
    float4 o;
    o.x = (v.x - mu) * rstd * g.x + bt.x;
    o.y = (v.y - mu) * rstd * g.y + bt.y;
    o.z = (v.z - mu) * rstd * g.z + bt.z;
    o.w = (v.w - mu) * rstd * g.w + bt.w;
    *reinterpret_cast<float4*>(out + (size_t)r * DIM + tid * 4) = o;
}

extern "C" void kernel_launch(void* const* d_in, const int* in_sizes, int n_in,
                              void* d_out, int out_size)
{
    const float* q     = (const float*)d_in[0];
    const int*   mask  = (const int*)  d_in[1];
    const float* k     = (const float*)d_in[2];
    const float* v     = (const float*)d_in[3];
    const float* Wq    = (const float*)d_in[4];
    const float* Wk    = (const float*)d_in[5];
    const float* Wv    = (const float*)d_in[6];
    const float* Wfc   = (const float*)d_in[7];
    const float* bfc   = (const float*)d_in[8];
    const float* gamma = (const float*)d_in[9];
    const float* beta  = (const float*)d_in[10];

    float* out      = (float*)d_out;                      // [B,L,D]
    float* mean_out = out + (size_t)NB * LSEQ * DIM;      // [B,L,L]

    dim3 thr(128);
    // projections: [4096,512] @ [512,4096]^T
    gemm_kernel<0, 0><<<dim3(32, 32, 1), thr>>>(q, Wq, nullptr, nullptr);
    gemm_kernel<0, 1><<<dim3(32, 32, 1), thr>>>(k, Wk, nullptr, nullptr);
    gemm_kernel<0, 2><<<dim3(32, 32, 1), thr>>>(v, Wv, nullptr, nullptr);
    // scores: per (b,h) [1024,512] @ [512,1024]
    gemm_kernel<1, 0><<<dim3(8, 8, 32), thr>>>(nullptr, nullptr, nullptr, nullptr);
    // masked softmax + renorm + head mean
    softmax_kernel<<<dim3(NB * LSEQ), 256>>>(mask, mean_out);
    // context: per (b,h) [1024,1024] @ [1024,512]
    gemm_kernel<2, 0><<<dim3(4, 8, 32), thr>>>(nullptr, nullptr, nullptr, nullptr);
    // fc + bias + residual
    gemm_kernel<3, 0><<<dim3(4, 32, 1), thr>>>(nullptr, Wfc, bfc, q);
    // layernorm -> final out
    ln_kernel<<<dim3(NB * LSEQ), 128>>>(gamma, beta, out);
}